// round 2
// baseline (speedup 1.0000x reference)
#include <cuda_runtime.h>
#include <cstdint>

// Problem constants
#define BB   4
#define SS   2048
#define DD   1024
#define HH   16
#define DKK  64

#define GM   (BB*SS)      // 8192
#define GK   DD
#define GN   DD

// ---------------------------------------------------------------------------
// Scratch (device globals)
// ---------------------------------------------------------------------------
__device__ float gQ[BB*SS*DD];   // rounded Q proj
__device__ float gK[BB*SS*DD];   // rounded K proj
__device__ float gV[BB*SS*DD];   // rounded V proj
__device__ float gC[BB*SS*DD];   // rounded ctx
__device__ float rQi[BB*SS*DD];  // rounded inputs
__device__ float rKi[BB*SS*DD];
__device__ float rVi[BB*SS*DD];
__device__ float rWq[DD*DD];
__device__ float rWk[DD*DD];
__device__ float rWv[DD*DD];
__device__ float rWo[DD*DD];

// ---------------------------------------------------------------------------
// Helpers
// ---------------------------------------------------------------------------
__device__ __forceinline__ unsigned f2tf(float f) {
    unsigned r;
    asm("cvt.rna.tf32.f32 %0, %1;" : "=r"(r) : "f"(f));
    return r;
}
__device__ __forceinline__ float ex2(float x) {
    float r;
    asm("ex2.approx.ftz.f32 %0, %1;" : "=f"(r) : "f"(x));
    return r;
}
__device__ __forceinline__ void mma_tf32(float& d0, float& d1, float& d2, float& d3,
                                         unsigned a0, unsigned a1, unsigned a2, unsigned a3,
                                         unsigned b0, unsigned b1) {
    asm("mma.sync.aligned.m16n8k8.row.col.f32.tf32.tf32.f32 "
        "{%0,%1,%2,%3},{%4,%5,%6,%7},{%8,%9},{%0,%1,%2,%3};"
        : "+f"(d0), "+f"(d1), "+f"(d2), "+f"(d3)
        : "r"(a0), "r"(a1), "r"(a2), "r"(a3), "r"(b0), "r"(b1));
}

// ---------------------------------------------------------------------------
// Elementwise RNA round to tf32-exact fp32
// ---------------------------------------------------------------------------
__global__ void round_kernel(const float4* __restrict__ src, float4* __restrict__ dst, int n4) {
    int i = blockIdx.x * blockDim.x + threadIdx.x;
    if (i < n4) {
        float4 v = src[i];
        v.x = __uint_as_float(f2tf(v.x));
        v.y = __uint_as_float(f2tf(v.y));
        v.z = __uint_as_float(f2tf(v.z));
        v.w = __uint_as_float(f2tf(v.w));
        dst[i] = v;
    }
}

// ---------------------------------------------------------------------------
// GEMM: C[M,N] = X[M,K] @ W[K,N] + bias[N]; X,W pre-rounded tf32-exact fp32.
// Block tile 128x128x32, 256 thr, cp.async 2-stage double buffer.
// ---------------------------------------------------------------------------
#define ASTR 36
#define BSTR 132
#define GEMM_SMEM ((2*128*ASTR + 2*32*BSTR) * 4)   // 70656 bytes

__global__ __launch_bounds__(256, 2)
void gemm_bias(const float* __restrict__ X, const float* __restrict__ W,
               const float* __restrict__ bias, float* __restrict__ C, int round_out) {
    extern __shared__ unsigned gsm[];
    unsigned* As = gsm;                    // [2][128*ASTR]
    unsigned* Bs = gsm + 2 * 128 * ASTR;   // [2][32*BSTR]

    const int tid  = threadIdx.x;
    const int wid  = tid >> 5;
    const int lane = tid & 31;
    const int g    = lane >> 2;
    const int t    = lane & 3;
    const int wm   = wid & 1;
    const int wn   = wid >> 1;
    const int m0   = blockIdx.y * 128;
    const int n0   = blockIdx.x * 128;
    const int NKT  = GK / 32;

    float acc[4][4][4];
#pragma unroll
    for (int mf = 0; mf < 4; mf++)
#pragma unroll
        for (int nf = 0; nf < 4; nf++)
#pragma unroll
            for (int r = 0; r < 4; r++) acc[mf][nf][r] = 0.f;

    auto issue = [&](int s, int kt) {
#pragma unroll
        for (int i = 0; i < 4; i++) {
            int idx = tid + i * 256;
            int r = idx >> 3, c4 = idx & 7;
            const float* gp = X + (size_t)(m0 + r) * GK + kt * 32 + c4 * 4;
            unsigned sa = (unsigned)__cvta_generic_to_shared(&As[s * 128 * ASTR + r * ASTR + c4 * 4]);
            asm volatile("cp.async.cg.shared.global [%0], [%1], 16;" :: "r"(sa), "l"(gp));
        }
#pragma unroll
        for (int i = 0; i < 4; i++) {
            int idx = tid + i * 256;
            int r = idx >> 5, c4 = idx & 31;
            const float* gp = W + (size_t)(kt * 32 + r) * GN + n0 + c4 * 4;
            unsigned sa = (unsigned)__cvta_generic_to_shared(&Bs[s * 32 * BSTR + r * BSTR + c4 * 4]);
            asm volatile("cp.async.cg.shared.global [%0], [%1], 16;" :: "r"(sa), "l"(gp));
        }
        asm volatile("cp.async.commit_group;");
    };

    issue(0, 0);
    issue(1, 1);

    for (int kt = 0; kt < NKT; kt++) {
        asm volatile("cp.async.wait_group 1;");
        __syncthreads();
        const unsigned* Ag = As + (kt & 1) * 128 * ASTR;
        const unsigned* Bg = Bs + (kt & 1) * 32 * BSTR;

#pragma unroll
        for (int ks = 0; ks < 4; ks++) {
            unsigned a[4][4];
#pragma unroll
            for (int mf = 0; mf < 4; mf++) {
                int rb = wm * 64 + mf * 16;
                a[mf][0] = Ag[(rb + g)     * ASTR + ks * 8 + t];
                a[mf][1] = Ag[(rb + g + 8) * ASTR + ks * 8 + t];
                a[mf][2] = Ag[(rb + g)     * ASTR + ks * 8 + t + 4];
                a[mf][3] = Ag[(rb + g + 8) * ASTR + ks * 8 + t + 4];
            }
#pragma unroll
            for (int nf = 0; nf < 4; nf++) {
                unsigned b0 = Bg[(ks * 8 + t)     * BSTR + wn * 32 + nf * 8 + g];
                unsigned b1 = Bg[(ks * 8 + t + 4) * BSTR + wn * 32 + nf * 8 + g];
#pragma unroll
                for (int mf = 0; mf < 4; mf++)
                    mma_tf32(acc[mf][nf][0], acc[mf][nf][1], acc[mf][nf][2], acc[mf][nf][3],
                             a[mf][0], a[mf][1], a[mf][2], a[mf][3], b0, b1);
            }
        }
        __syncthreads();
        if (kt + 2 < NKT) issue(kt & 1, kt + 2);
        else asm volatile("cp.async.commit_group;");
    }

#pragma unroll
    for (int mf = 0; mf < 4; mf++) {
#pragma unroll
        for (int nf = 0; nf < 4; nf++) {
            int row = m0 + wm * 64 + mf * 16 + g;
            int col = n0 + wn * 32 + nf * 8 + 2 * t;
            float bv0 = bias[col], bv1 = bias[col + 1];
            float v00 = acc[mf][nf][0] + bv0;
            float v01 = acc[mf][nf][1] + bv1;
            float v10 = acc[mf][nf][2] + bv0;
            float v11 = acc[mf][nf][3] + bv1;
            if (round_out) {
                v00 = __uint_as_float(f2tf(v00));
                v01 = __uint_as_float(f2tf(v01));
                v10 = __uint_as_float(f2tf(v10));
                v11 = __uint_as_float(f2tf(v11));
            }
            C[(size_t)row * GN + col]           = v00;
            C[(size_t)row * GN + col + 1]       = v01;
            C[(size_t)(row + 8) * GN + col]     = v10;
            C[(size_t)(row + 8) * GN + col + 1] = v11;
        }
    }
}

// ---------------------------------------------------------------------------
// Flash attention v2.
// grid (S/128, H, B), 256 thr. Warp w owns q rows [w*16, w*16+16).
// K staged k-permuted (c' = (c&7)*8 + c>>3, stride 68) -> 4x LDS.128 per nf
// fetches all 8 k-step B-fragments. V staged plain. P never touches smem:
// S-accumulator fragments are permuted to PV A-fragments with quad shuffles.
// ---------------------------------------------------------------------------
#define KST 68
#define ATTN_SMEM ((128*KST + 128*KST) * 4)   // 69632 bytes

__global__ __launch_bounds__(256, 1)
void attn_kernel(const float* __restrict__ gq, const float* __restrict__ gk,
                 const float* __restrict__ gv, float* __restrict__ gc) {
    extern __shared__ unsigned sm[];
    unsigned* Ks = sm;              // permuted [128][KST]
    unsigned* Vs = sm + 128 * KST;  // plain    [128][KST]

    const int b  = blockIdx.z;
    const int h  = blockIdx.y;
    const int q0 = blockIdx.x * 128;
    const int tid  = threadIdx.x;
    const int wid  = tid >> 5;
    const int lane = tid & 31;
    const int g    = lane >> 2;
    const int t    = lane & 3;
    const int qb   = lane & ~3;
    const float L2E = 1.44269504f;

    // Q fragments (pre-rounded; *0.125 is exact in tf32)
    unsigned qf[8][4];
    {
        const float* Qb = gq + ((size_t)(b * SS + q0 + wid * 16)) * DD + h * DKK;
#pragma unroll
        for (int ks = 0; ks < 8; ks++) {
            qf[ks][0] = __float_as_uint(Qb[(size_t)g * DD + ks * 8 + t] * 0.125f);
            qf[ks][1] = __float_as_uint(Qb[(size_t)(g + 8) * DD + ks * 8 + t] * 0.125f);
            qf[ks][2] = __float_as_uint(Qb[(size_t)g * DD + ks * 8 + t + 4] * 0.125f);
            qf[ks][3] = __float_as_uint(Qb[(size_t)(g + 8) * DD + ks * 8 + t + 4] * 0.125f);
        }
    }

    float mr0 = -1e30f, mr1 = -1e30f, l0 = 0.f, l1 = 0.f;
    float oacc[8][4];
#pragma unroll
    for (int nf = 0; nf < 8; nf++)
#pragma unroll
        for (int r = 0; r < 4; r++) oacc[nf][r] = 0.f;

    const uint4* Kb = (const uint4*)(gk + (size_t)b * SS * DD + h * DKK);
    const uint4* Vb = (const uint4*)(gv + (size_t)b * SS * DD + h * DKK);
    const int RSTR4 = DD / 4;   // uint4 row stride

    for (int kt = 0; kt < SS / 128; kt++) {
        __syncthreads();
        // staging: K permuted, V plain (both pre-rounded raw bits)
#pragma unroll
        for (int i = 0; i < 8; i++) {
            int idx = tid + i * 256;
            int r = idx >> 4, c4 = idx & 15, c = c4 * 4;
            uint4 kv = Kb[(size_t)(kt * 128 + r) * RSTR4 + c4];
            int base = r * KST;
            Ks[base + ((c + 0) & 7) * 8 + ((c + 0) >> 3)] = kv.x;
            Ks[base + ((c + 1) & 7) * 8 + ((c + 1) >> 3)] = kv.y;
            Ks[base + ((c + 2) & 7) * 8 + ((c + 2) >> 3)] = kv.z;
            Ks[base + ((c + 3) & 7) * 8 + ((c + 3) >> 3)] = kv.w;
            uint4 vv = Vb[(size_t)(kt * 128 + r) * RSTR4 + c4];
            *(uint4*)&Vs[base + c] = vv;
        }
        __syncthreads();

        // S = Q K^T (scale folded into Q): 16 x 128 per warp
        float sacc[16][4];
#pragma unroll
        for (int nf = 0; nf < 16; nf++)
#pragma unroll
            for (int r = 0; r < 4; r++) sacc[nf][r] = 0.f;

#pragma unroll
        for (int nf = 0; nf < 16; nf++) {
            const uint4* kp = (const uint4*)&Ks[(nf * 8 + g) * KST + t * 8];
            uint4 k0 = kp[0], k1 = kp[1];
            const uint4* kq = (const uint4*)&Ks[(nf * 8 + g) * KST + (t + 4) * 8];
            uint4 k2 = kq[0], k3 = kq[1];
            mma_tf32(sacc[nf][0], sacc[nf][1], sacc[nf][2], sacc[nf][3],
                     qf[0][0], qf[0][1], qf[0][2], qf[0][3], k0.x, k2.x);
            mma_tf32(sacc[nf][0], sacc[nf][1], sacc[nf][2], sacc[nf][3],
                     qf[1][0], qf[1][1], qf[1][2], qf[1][3], k0.y, k2.y);
            mma_tf32(sacc[nf][0], sacc[nf][1], sacc[nf][2], sacc[nf][3],
                     qf[2][0], qf[2][1], qf[2][2], qf[2][3], k0.z, k2.z);
            mma_tf32(sacc[nf][0], sacc[nf][1], sacc[nf][2], sacc[nf][3],
                     qf[3][0], qf[3][1], qf[3][2], qf[3][3], k0.w, k2.w);
            mma_tf32(sacc[nf][0], sacc[nf][1], sacc[nf][2], sacc[nf][3],
                     qf[4][0], qf[4][1], qf[4][2], qf[4][3], k1.x, k3.x);
            mma_tf32(sacc[nf][0], sacc[nf][1], sacc[nf][2], sacc[nf][3],
                     qf[5][0], qf[5][1], qf[5][2], qf[5][3], k1.y, k3.y);
            mma_tf32(sacc[nf][0], sacc[nf][1], sacc[nf][2], sacc[nf][3],
                     qf[6][0], qf[6][1], qf[6][2], qf[6][3], k1.z, k3.z);
            mma_tf32(sacc[nf][0], sacc[nf][1], sacc[nf][2], sacc[nf][3],
                     qf[7][0], qf[7][1], qf[7][2], qf[7][3], k1.w, k3.w);
        }

        // online softmax
        float rmax0 = -1e30f, rmax1 = -1e30f;
#pragma unroll
        for (int nf = 0; nf < 16; nf++) {
            rmax0 = fmaxf(rmax0, fmaxf(sacc[nf][0], sacc[nf][1]));
            rmax1 = fmaxf(rmax1, fmaxf(sacc[nf][2], sacc[nf][3]));
        }
        rmax0 = fmaxf(rmax0, __shfl_xor_sync(0xffffffffu, rmax0, 1));
        rmax0 = fmaxf(rmax0, __shfl_xor_sync(0xffffffffu, rmax0, 2));
        rmax1 = fmaxf(rmax1, __shfl_xor_sync(0xffffffffu, rmax1, 1));
        rmax1 = fmaxf(rmax1, __shfl_xor_sync(0xffffffffu, rmax1, 2));
        float mn0 = fmaxf(mr0, rmax0), mn1 = fmaxf(mr1, rmax1);
        float alpha0 = ex2((mr0 - mn0) * L2E);
        float alpha1 = ex2((mr1 - mn1) * L2E);
        mr0 = mn0; mr1 = mn1;

        // exp + quad-shuffle permute acc-fragment -> A-fragment (no smem)
        unsigned pa[16][4];
        float rs0 = 0.f, rs1 = 0.f;
        const int s0 = qb | (t >> 1);
        const int s1 = s0 + 2;
        const bool odd = (t & 1);
#pragma unroll
        for (int nf = 0; nf < 16; nf++) {
            float p0 = ex2((sacc[nf][0] - mn0) * L2E);
            float p1 = ex2((sacc[nf][1] - mn0) * L2E);
            float p2 = ex2((sacc[nf][2] - mn1) * L2E);
            float p3 = ex2((sacc[nf][3] - mn1) * L2E);
            rs0 += p0 + p1;
            rs1 += p2 + p3;
            float y00 = __shfl_sync(0xffffffffu, p0, s0);
            float y01 = __shfl_sync(0xffffffffu, p1, s0);
            float y10 = __shfl_sync(0xffffffffu, p2, s0);
            float y11 = __shfl_sync(0xffffffffu, p3, s0);
            float z00 = __shfl_sync(0xffffffffu, p0, s1);
            float z01 = __shfl_sync(0xffffffffu, p1, s1);
            float z10 = __shfl_sync(0xffffffffu, p2, s1);
            float z11 = __shfl_sync(0xffffffffu, p3, s1);
            pa[nf][0] = f2tf(odd ? y01 : y00);   // (row g,   col t)
            pa[nf][1] = f2tf(odd ? y11 : y10);   // (row g+8, col t)
            pa[nf][2] = f2tf(odd ? z01 : z00);   // (row g,   col t+4)
            pa[nf][3] = f2tf(odd ? z11 : z10);   // (row g+8, col t+4)
        }
        rs0 += __shfl_xor_sync(0xffffffffu, rs0, 1);
        rs0 += __shfl_xor_sync(0xffffffffu, rs0, 2);
        rs1 += __shfl_xor_sync(0xffffffffu, rs1, 1);
        rs1 += __shfl_xor_sync(0xffffffffu, rs1, 2);
        l0 = l0 * alpha0 + rs0;
        l1 = l1 * alpha1 + rs1;
#pragma unroll
        for (int nf = 0; nf < 8; nf++) {
            oacc[nf][0] *= alpha0; oacc[nf][1] *= alpha0;
            oacc[nf][2] *= alpha1; oacc[nf][3] *= alpha1;
        }

        // O += P V
#pragma unroll
        for (int nf = 0; nf < 8; nf++) {
#pragma unroll
            for (int ks = 0; ks < 16; ks++) {
                unsigned b0 = Vs[(ks * 8 + t)     * KST + nf * 8 + g];
                unsigned b1 = Vs[(ks * 8 + t + 4) * KST + nf * 8 + g];
                mma_tf32(oacc[nf][0], oacc[nf][1], oacc[nf][2], oacc[nf][3],
                         pa[ks][0], pa[ks][1], pa[ks][2], pa[ks][3], b0, b1);
            }
        }
    }

    // epilogue: normalize + round (ctx feeds the tf32 O-projection)
    float inv0 = 1.f / l0, inv1 = 1.f / l1;
    float* Cb = gc + ((size_t)(b * SS + q0 + wid * 16)) * DD + h * DKK;
#pragma unroll
    for (int nf = 0; nf < 8; nf++) {
        int c = nf * 8 + 2 * t;
        Cb[(size_t)g * DD + c]           = __uint_as_float(f2tf(oacc[nf][0] * inv0));
        Cb[(size_t)g * DD + c + 1]       = __uint_as_float(f2tf(oacc[nf][1] * inv0));
        Cb[(size_t)(g + 8) * DD + c]     = __uint_as_float(f2tf(oacc[nf][2] * inv1));
        Cb[(size_t)(g + 8) * DD + c + 1] = __uint_as_float(f2tf(oacc[nf][3] * inv1));
    }
}

// ---------------------------------------------------------------------------
// Launch
// ---------------------------------------------------------------------------
extern "C" void kernel_launch(void* const* d_in, const int* in_sizes, int n_in,
                              void* d_out, int out_size) {
    const float* query = (const float*)d_in[0];
    const float* key_  = (const float*)d_in[1];
    const float* value = (const float*)d_in[2];
    const float* Wq = (const float*)d_in[3];
    const float* bq = (const float*)d_in[4];
    const float* Wk = (const float*)d_in[5];
    const float* bk = (const float*)d_in[6];
    const float* Wv = (const float*)d_in[7];
    const float* bv = (const float*)d_in[8];
    const float* Wo = (const float*)d_in[9];
    const float* bo = (const float*)d_in[10];
    float* out = (float*)d_out;

    float *pQ, *pK, *pV, *pC, *prQ, *prK, *prV, *pWq, *pWk, *pWv, *pWo;
    cudaGetSymbolAddress((void**)&pQ, gQ);
    cudaGetSymbolAddress((void**)&pK, gK);
    cudaGetSymbolAddress((void**)&pV, gV);
    cudaGetSymbolAddress((void**)&pC, gC);
    cudaGetSymbolAddress((void**)&prQ, rQi);
    cudaGetSymbolAddress((void**)&prK, rKi);
    cudaGetSymbolAddress((void**)&prV, rVi);
    cudaGetSymbolAddress((void**)&pWq, rWq);
    cudaGetSymbolAddress((void**)&pWk, rWk);
    cudaGetSymbolAddress((void**)&pWv, rWv);
    cudaGetSymbolAddress((void**)&pWo, rWo);

    cudaFuncSetAttribute(gemm_bias, cudaFuncAttributeMaxDynamicSharedMemorySize, GEMM_SMEM);
    cudaFuncSetAttribute(attn_kernel, cudaFuncAttributeMaxDynamicSharedMemorySize, ATTN_SMEM);

    // pre-round inputs + weights to tf32-exact fp32
    const int nX4 = GM * DD / 4, nW4 = DD * DD / 4;
    round_kernel<<<(nX4 + 255) / 256, 256>>>((const float4*)query, (float4*)prQ, nX4);
    round_kernel<<<(nX4 + 255) / 256, 256>>>((const float4*)key_,  (float4*)prK, nX4);
    round_kernel<<<(nX4 + 255) / 256, 256>>>((const float4*)value, (float4*)prV, nX4);
    round_kernel<<<(nW4 + 255) / 256, 256>>>((const float4*)Wq, (float4*)pWq, nW4);
    round_kernel<<<(nW4 + 255) / 256, 256>>>((const float4*)Wk, (float4*)pWk, nW4);
    round_kernel<<<(nW4 + 255) / 256, 256>>>((const float4*)Wv, (float4*)pWv, nW4);
    round_kernel<<<(nW4 + 255) / 256, 256>>>((const float4*)Wo, (float4*)pWo, nW4);

    dim3 ggrid(GN / 128, GM / 128);   // (8, 64)
    gemm_bias<<<ggrid, 256, GEMM_SMEM>>>(prQ, pWq, bq, pQ, 1);
    gemm_bias<<<ggrid, 256, GEMM_SMEM>>>(prK, pWk, bk, pK, 1);
    gemm_bias<<<ggrid, 256, GEMM_SMEM>>>(prV, pWv, bv, pV, 1);

    attn_kernel<<<dim3(SS / 128, HH, BB), 256, ATTN_SMEM>>>(pQ, pK, pV, pC);

    gemm_bias<<<ggrid, 256, GEMM_SMEM>>>(pC, pWo, bo, out, 0);
}

// round 3
// speedup vs baseline: 1.0071x; 1.0071x over previous
#include <cuda_runtime.h>
#include <cstdint>

// Problem constants
#define BB   4
#define SS   2048
#define DD   1024
#define HH   16
#define DKK  64

#define GM   (BB*SS)      // 8192
#define GK   DD
#define GN   DD

// ---------------------------------------------------------------------------
// Scratch (device globals)
// ---------------------------------------------------------------------------
__device__ float gQ[BB*SS*DD];
__device__ float gK[BB*SS*DD];
__device__ float gV[BB*SS*DD];
__device__ float gC[BB*SS*DD];
__device__ float rQi[BB*SS*DD];
__device__ float rKi[BB*SS*DD];
__device__ float rVi[BB*SS*DD];
__device__ float rWq[DD*DD];
__device__ float rWk[DD*DD];
__device__ float rWv[DD*DD];
__device__ float rWo[DD*DD];

// ---------------------------------------------------------------------------
// Helpers
// ---------------------------------------------------------------------------
__device__ __forceinline__ unsigned f2tf(float f) {
    unsigned r;
    asm("cvt.rna.tf32.f32 %0, %1;" : "=r"(r) : "f"(f));
    return r;
}
__device__ __forceinline__ float ex2(float x) {
    float r;
    asm("ex2.approx.ftz.f32 %0, %1;" : "=f"(r) : "f"(x));
    return r;
}
__device__ __forceinline__ void mma_tf32(float& d0, float& d1, float& d2, float& d3,
                                         unsigned a0, unsigned a1, unsigned a2, unsigned a3,
                                         unsigned b0, unsigned b1) {
    asm("mma.sync.aligned.m16n8k8.row.col.f32.tf32.tf32.f32 "
        "{%0,%1,%2,%3},{%4,%5,%6,%7},{%8,%9},{%0,%1,%2,%3};"
        : "+f"(d0), "+f"(d1), "+f"(d2), "+f"(d3)
        : "r"(a0), "r"(a1), "r"(a2), "r"(a3), "r"(b0), "r"(b1));
}

// ---------------------------------------------------------------------------
// One-launch rounding of all 7 tensors (RNA round to tf32-exact fp32).
// grid: (8192, 7). Segments 0-2: inputs (2M float4). 3-6: weights (256K).
// ---------------------------------------------------------------------------
struct RoundArgs {
    const float4* src[7];
    float4*       dst[7];
    int           n4[7];
};

__global__ __launch_bounds__(256)
void round_all(RoundArgs a) {
    int seg = blockIdx.y;
    int i = blockIdx.x * blockDim.x + threadIdx.x;
    if (i < a.n4[seg]) {
        float4 v = a.src[seg][i];
        v.x = __uint_as_float(f2tf(v.x));
        v.y = __uint_as_float(f2tf(v.y));
        v.z = __uint_as_float(f2tf(v.z));
        v.w = __uint_as_float(f2tf(v.w));
        a.dst[seg][i] = v;
    }
}

// ---------------------------------------------------------------------------
// GEMM: C[M,N] = X[M,K] @ W[K,N] + bias[N]; X,W pre-rounded tf32-exact fp32.
// Block tile 128x128x32, 256 thr, cp.async 2-stage double buffer.
// NOTE: no min-blocks clause — reg cap at 128 caused spills in round 2.
// ---------------------------------------------------------------------------
#define ASTR 36
#define BSTR 132
#define GEMM_SMEM ((2*128*ASTR + 2*32*BSTR) * 4)   // 70656 bytes

__global__ __launch_bounds__(256)
void gemm_bias(const float* __restrict__ X, const float* __restrict__ W,
               const float* __restrict__ bias, float* __restrict__ C, int round_out) {
    extern __shared__ unsigned gsm[];
    unsigned* As = gsm;                    // [2][128*ASTR]
    unsigned* Bs = gsm + 2 * 128 * ASTR;   // [2][32*BSTR]

    const int tid  = threadIdx.x;
    const int wid  = tid >> 5;
    const int lane = tid & 31;
    const int g    = lane >> 2;
    const int t    = lane & 3;
    const int wm   = wid & 1;
    const int wn   = wid >> 1;
    const int m0   = blockIdx.y * 128;
    const int n0   = blockIdx.x * 128;
    const int NKT  = GK / 32;

    float acc[4][4][4];
#pragma unroll
    for (int mf = 0; mf < 4; mf++)
#pragma unroll
        for (int nf = 0; nf < 4; nf++)
#pragma unroll
            for (int r = 0; r < 4; r++) acc[mf][nf][r] = 0.f;

    auto issue = [&](int s, int kt) {
#pragma unroll
        for (int i = 0; i < 4; i++) {
            int idx = tid + i * 256;
            int r = idx >> 3, c4 = idx & 7;
            const float* gp = X + (size_t)(m0 + r) * GK + kt * 32 + c4 * 4;
            unsigned sa = (unsigned)__cvta_generic_to_shared(&As[s * 128 * ASTR + r * ASTR + c4 * 4]);
            asm volatile("cp.async.cg.shared.global [%0], [%1], 16;" :: "r"(sa), "l"(gp));
        }
#pragma unroll
        for (int i = 0; i < 4; i++) {
            int idx = tid + i * 256;
            int r = idx >> 5, c4 = idx & 31;
            const float* gp = W + (size_t)(kt * 32 + r) * GN + n0 + c4 * 4;
            unsigned sa = (unsigned)__cvta_generic_to_shared(&Bs[s * 32 * BSTR + r * BSTR + c4 * 4]);
            asm volatile("cp.async.cg.shared.global [%0], [%1], 16;" :: "r"(sa), "l"(gp));
        }
        asm volatile("cp.async.commit_group;");
    };

    issue(0, 0);
    issue(1, 1);

    for (int kt = 0; kt < NKT; kt++) {
        asm volatile("cp.async.wait_group 1;");
        __syncthreads();
        const unsigned* Ag = As + (kt & 1) * 128 * ASTR;
        const unsigned* Bg = Bs + (kt & 1) * 32 * BSTR;

#pragma unroll
        for (int ks = 0; ks < 4; ks++) {
            unsigned a[4][4];
#pragma unroll
            for (int mf = 0; mf < 4; mf++) {
                int rb = wm * 64 + mf * 16;
                a[mf][0] = Ag[(rb + g)     * ASTR + ks * 8 + t];
                a[mf][1] = Ag[(rb + g + 8) * ASTR + ks * 8 + t];
                a[mf][2] = Ag[(rb + g)     * ASTR + ks * 8 + t + 4];
                a[mf][3] = Ag[(rb + g + 8) * ASTR + ks * 8 + t + 4];
            }
#pragma unroll
            for (int nf = 0; nf < 4; nf++) {
                unsigned b0 = Bg[(ks * 8 + t)     * BSTR + wn * 32 + nf * 8 + g];
                unsigned b1 = Bg[(ks * 8 + t + 4) * BSTR + wn * 32 + nf * 8 + g];
#pragma unroll
                for (int mf = 0; mf < 4; mf++)
                    mma_tf32(acc[mf][nf][0], acc[mf][nf][1], acc[mf][nf][2], acc[mf][nf][3],
                             a[mf][0], a[mf][1], a[mf][2], a[mf][3], b0, b1);
            }
        }
        __syncthreads();
        if (kt + 2 < NKT) issue(kt & 1, kt + 2);
        else asm volatile("cp.async.commit_group;");
    }

#pragma unroll
    for (int mf = 0; mf < 4; mf++) {
#pragma unroll
        for (int nf = 0; nf < 4; nf++) {
            int row = m0 + wm * 64 + mf * 16 + g;
            int col = n0 + wn * 32 + nf * 8 + 2 * t;
            float bv0 = bias[col], bv1 = bias[col + 1];
            float v00 = acc[mf][nf][0] + bv0;
            float v01 = acc[mf][nf][1] + bv1;
            float v10 = acc[mf][nf][2] + bv0;
            float v11 = acc[mf][nf][3] + bv1;
            if (round_out) {
                v00 = __uint_as_float(f2tf(v00));
                v01 = __uint_as_float(f2tf(v01));
                v10 = __uint_as_float(f2tf(v10));
                v11 = __uint_as_float(f2tf(v11));
            }
            C[(size_t)row * GN + col]           = v00;
            C[(size_t)row * GN + col + 1]       = v01;
            C[(size_t)(row + 8) * GN + col]     = v10;
            C[(size_t)(row + 8) * GN + col + 1] = v11;
        }
    }
}

// ---------------------------------------------------------------------------
// Flash attention v3: same dataflow as v2 but the S accumulator is converted
// to the PV A-fragment IN PLACE (no pa[] array) to avoid register spills.
// ---------------------------------------------------------------------------
#define KST 68
#define ATTN_SMEM ((128*KST + 128*KST) * 4)   // 69632 bytes

__global__ __launch_bounds__(256)
void attn_kernel(const float* __restrict__ gq, const float* __restrict__ gk,
                 const float* __restrict__ gv, float* __restrict__ gc) {
    extern __shared__ unsigned sm[];
    unsigned* Ks = sm;              // permuted [128][KST]
    unsigned* Vs = sm + 128 * KST;  // plain    [128][KST]

    const int b  = blockIdx.z;
    const int h  = blockIdx.y;
    const int q0 = blockIdx.x * 128;
    const int tid  = threadIdx.x;
    const int wid  = tid >> 5;
    const int lane = tid & 31;
    const int g    = lane >> 2;
    const int t    = lane & 3;
    const int qb   = lane & ~3;
    const float L2E = 1.44269504f;

    // Q fragments (pre-rounded; *0.125 exact in tf32)
    unsigned qf[8][4];
    {
        const float* Qb = gq + ((size_t)(b * SS + q0 + wid * 16)) * DD + h * DKK;
#pragma unroll
        for (int ks = 0; ks < 8; ks++) {
            qf[ks][0] = __float_as_uint(Qb[(size_t)g * DD + ks * 8 + t] * 0.125f);
            qf[ks][1] = __float_as_uint(Qb[(size_t)(g + 8) * DD + ks * 8 + t] * 0.125f);
            qf[ks][2] = __float_as_uint(Qb[(size_t)g * DD + ks * 8 + t + 4] * 0.125f);
            qf[ks][3] = __float_as_uint(Qb[(size_t)(g + 8) * DD + ks * 8 + t + 4] * 0.125f);
        }
    }

    float mr0 = -1e30f, mr1 = -1e30f, l0 = 0.f, l1 = 0.f;
    float oacc[8][4];
#pragma unroll
    for (int nf = 0; nf < 8; nf++)
#pragma unroll
        for (int r = 0; r < 4; r++) oacc[nf][r] = 0.f;

    const uint4* Kb = (const uint4*)(gk + (size_t)b * SS * DD + h * DKK);
    const uint4* Vb = (const uint4*)(gv + (size_t)b * SS * DD + h * DKK);
    const int RSTR4 = DD / 4;

    for (int kt = 0; kt < SS / 128; kt++) {
        __syncthreads();
#pragma unroll
        for (int i = 0; i < 8; i++) {
            int idx = tid + i * 256;
            int r = idx >> 4, c4 = idx & 15, c = c4 * 4;
            uint4 kv = Kb[(size_t)(kt * 128 + r) * RSTR4 + c4];
            int base = r * KST;
            Ks[base + ((c + 0) & 7) * 8 + ((c + 0) >> 3)] = kv.x;
            Ks[base + ((c + 1) & 7) * 8 + ((c + 1) >> 3)] = kv.y;
            Ks[base + ((c + 2) & 7) * 8 + ((c + 2) >> 3)] = kv.z;
            Ks[base + ((c + 3) & 7) * 8 + ((c + 3) >> 3)] = kv.w;
            uint4 vv = Vb[(size_t)(kt * 128 + r) * RSTR4 + c4];
            *(uint4*)&Vs[base + c] = vv;
        }
        __syncthreads();

        // S = Q K^T : 16 x 128 per warp
        float sacc[16][4];
#pragma unroll
        for (int nf = 0; nf < 16; nf++)
#pragma unroll
            for (int r = 0; r < 4; r++) sacc[nf][r] = 0.f;

#pragma unroll
        for (int nf = 0; nf < 16; nf++) {
            const uint4* kp = (const uint4*)&Ks[(nf * 8 + g) * KST + t * 8];
            uint4 k0 = kp[0], k1 = kp[1];
            const uint4* kq = (const uint4*)&Ks[(nf * 8 + g) * KST + (t + 4) * 8];
            uint4 k2 = kq[0], k3 = kq[1];
            mma_tf32(sacc[nf][0], sacc[nf][1], sacc[nf][2], sacc[nf][3],
                     qf[0][0], qf[0][1], qf[0][2], qf[0][3], k0.x, k2.x);
            mma_tf32(sacc[nf][0], sacc[nf][1], sacc[nf][2], sacc[nf][3],
                     qf[1][0], qf[1][1], qf[1][2], qf[1][3], k0.y, k2.y);
            mma_tf32(sacc[nf][0], sacc[nf][1], sacc[nf][2], sacc[nf][3],
                     qf[2][0], qf[2][1], qf[2][2], qf[2][3], k0.z, k2.z);
            mma_tf32(sacc[nf][0], sacc[nf][1], sacc[nf][2], sacc[nf][3],
                     qf[3][0], qf[3][1], qf[3][2], qf[3][3], k0.w, k2.w);
            mma_tf32(sacc[nf][0], sacc[nf][1], sacc[nf][2], sacc[nf][3],
                     qf[4][0], qf[4][1], qf[4][2], qf[4][3], k1.x, k3.x);
            mma_tf32(sacc[nf][0], sacc[nf][1], sacc[nf][2], sacc[nf][3],
                     qf[5][0], qf[5][1], qf[5][2], qf[5][3], k1.y, k3.y);
            mma_tf32(sacc[nf][0], sacc[nf][1], sacc[nf][2], sacc[nf][3],
                     qf[6][0], qf[6][1], qf[6][2], qf[6][3], k1.z, k3.z);
            mma_tf32(sacc[nf][0], sacc[nf][1], sacc[nf][2], sacc[nf][3],
                     qf[7][0], qf[7][1], qf[7][2], qf[7][3], k1.w, k3.w);
        }

        // online softmax
        float rmax0 = -1e30f, rmax1 = -1e30f;
#pragma unroll
        for (int nf = 0; nf < 16; nf++) {
            rmax0 = fmaxf(rmax0, fmaxf(sacc[nf][0], sacc[nf][1]));
            rmax1 = fmaxf(rmax1, fmaxf(sacc[nf][2], sacc[nf][3]));
        }
        rmax0 = fmaxf(rmax0, __shfl_xor_sync(0xffffffffu, rmax0, 1));
        rmax0 = fmaxf(rmax0, __shfl_xor_sync(0xffffffffu, rmax0, 2));
        rmax1 = fmaxf(rmax1, __shfl_xor_sync(0xffffffffu, rmax1, 1));
        rmax1 = fmaxf(rmax1, __shfl_xor_sync(0xffffffffu, rmax1, 2));
        float mn0 = fmaxf(mr0, rmax0), mn1 = fmaxf(mr1, rmax1);
        float alpha0 = ex2((mr0 - mn0) * L2E);
        float alpha1 = ex2((mr1 - mn1) * L2E);
        mr0 = mn0; mr1 = mn1;

        // exp + quad-shuffle; convert sacc fragment -> A-fragment IN PLACE
        float rs0 = 0.f, rs1 = 0.f;
        const int s0 = qb | (t >> 1);
        const int s1 = s0 + 2;
        const bool odd = (t & 1);
#pragma unroll
        for (int nf = 0; nf < 16; nf++) {
            float p0 = ex2((sacc[nf][0] - mn0) * L2E);
            float p1 = ex2((sacc[nf][1] - mn0) * L2E);
            float p2 = ex2((sacc[nf][2] - mn1) * L2E);
            float p3 = ex2((sacc[nf][3] - mn1) * L2E);
            rs0 += p0 + p1;
            rs1 += p2 + p3;
            float y00 = __shfl_sync(0xffffffffu, p0, s0);
            float y01 = __shfl_sync(0xffffffffu, p1, s0);
            float y10 = __shfl_sync(0xffffffffu, p2, s0);
            float y11 = __shfl_sync(0xffffffffu, p3, s0);
            float z00 = __shfl_sync(0xffffffffu, p0, s1);
            float z01 = __shfl_sync(0xffffffffu, p1, s1);
            float z10 = __shfl_sync(0xffffffffu, p2, s1);
            float z11 = __shfl_sync(0xffffffffu, p3, s1);
            sacc[nf][0] = __uint_as_float(f2tf(odd ? y01 : y00));
            sacc[nf][1] = __uint_as_float(f2tf(odd ? y11 : y10));
            sacc[nf][2] = __uint_as_float(f2tf(odd ? z01 : z00));
            sacc[nf][3] = __uint_as_float(f2tf(odd ? z11 : z10));
        }
        rs0 += __shfl_xor_sync(0xffffffffu, rs0, 1);
        rs0 += __shfl_xor_sync(0xffffffffu, rs0, 2);
        rs1 += __shfl_xor_sync(0xffffffffu, rs1, 1);
        rs1 += __shfl_xor_sync(0xffffffffu, rs1, 2);
        l0 = l0 * alpha0 + rs0;
        l1 = l1 * alpha1 + rs1;
#pragma unroll
        for (int nf = 0; nf < 8; nf++) {
            oacc[nf][0] *= alpha0; oacc[nf][1] *= alpha0;
            oacc[nf][2] *= alpha1; oacc[nf][3] *= alpha1;
        }

        // O += P V  (A fragments read from the converted sacc)
#pragma unroll
        for (int nf = 0; nf < 8; nf++) {
#pragma unroll
            for (int ks = 0; ks < 16; ks++) {
                unsigned a0 = __float_as_uint(sacc[ks][0]);
                unsigned a1 = __float_as_uint(sacc[ks][1]);
                unsigned a2 = __float_as_uint(sacc[ks][2]);
                unsigned a3 = __float_as_uint(sacc[ks][3]);
                unsigned b0 = Vs[(ks * 8 + t)     * KST + nf * 8 + g];
                unsigned b1 = Vs[(ks * 8 + t + 4) * KST + nf * 8 + g];
                mma_tf32(oacc[nf][0], oacc[nf][1], oacc[nf][2], oacc[nf][3],
                         a0, a1, a2, a3, b0, b1);
            }
        }
    }

    // epilogue: normalize + round (ctx feeds the tf32 O-projection)
    float inv0 = 1.f / l0, inv1 = 1.f / l1;
    float* Cb = gc + ((size_t)(b * SS + q0 + wid * 16)) * DD + h * DKK;
#pragma unroll
    for (int nf = 0; nf < 8; nf++) {
        int c = nf * 8 + 2 * t;
        Cb[(size_t)g * DD + c]           = __uint_as_float(f2tf(oacc[nf][0] * inv0));
        Cb[(size_t)g * DD + c + 1]       = __uint_as_float(f2tf(oacc[nf][1] * inv0));
        Cb[(size_t)(g + 8) * DD + c]     = __uint_as_float(f2tf(oacc[nf][2] * inv1));
        Cb[(size_t)(g + 8) * DD + c + 1] = __uint_as_float(f2tf(oacc[nf][3] * inv1));
    }
}

// ---------------------------------------------------------------------------
// Launch
// ---------------------------------------------------------------------------
extern "C" void kernel_launch(void* const* d_in, const int* in_sizes, int n_in,
                              void* d_out, int out_size) {
    const float* query = (const float*)d_in[0];
    const float* key_  = (const float*)d_in[1];
    const float* value = (const float*)d_in[2];
    const float* Wq = (const float*)d_in[3];
    const float* bq = (const float*)d_in[4];
    const float* Wk = (const float*)d_in[5];
    const float* bk = (const float*)d_in[6];
    const float* Wv = (const float*)d_in[7];
    const float* bv = (const float*)d_in[8];
    const float* Wo = (const float*)d_in[9];
    const float* bo = (const float*)d_in[10];
    float* out = (float*)d_out;

    float *pQ, *pK, *pV, *pC, *prQ, *prK, *prV, *pWq, *pWk, *pWv, *pWo;
    cudaGetSymbolAddress((void**)&pQ, gQ);
    cudaGetSymbolAddress((void**)&pK, gK);
    cudaGetSymbolAddress((void**)&pV, gV);
    cudaGetSymbolAddress((void**)&pC, gC);
    cudaGetSymbolAddress((void**)&prQ, rQi);
    cudaGetSymbolAddress((void**)&prK, rKi);
    cudaGetSymbolAddress((void**)&prV, rVi);
    cudaGetSymbolAddress((void**)&pWq, rWq);
    cudaGetSymbolAddress((void**)&pWk, rWk);
    cudaGetSymbolAddress((void**)&pWv, rWv);
    cudaGetSymbolAddress((void**)&pWo, rWo);

    cudaFuncSetAttribute(gemm_bias, cudaFuncAttributeMaxDynamicSharedMemorySize, GEMM_SMEM);
    cudaFuncSetAttribute(attn_kernel, cudaFuncAttributeMaxDynamicSharedMemorySize, ATTN_SMEM);

    const int nX4 = GM * DD / 4, nW4 = DD * DD / 4;
    RoundArgs ra;
    ra.src[0] = (const float4*)query; ra.dst[0] = (float4*)prQ; ra.n4[0] = nX4;
    ra.src[1] = (const float4*)key_;  ra.dst[1] = (float4*)prK; ra.n4[1] = nX4;
    ra.src[2] = (const float4*)value; ra.dst[2] = (float4*)prV; ra.n4[2] = nX4;
    ra.src[3] = (const float4*)Wq;    ra.dst[3] = (float4*)pWq; ra.n4[3] = nW4;
    ra.src[4] = (const float4*)Wk;    ra.dst[4] = (float4*)pWk; ra.n4[4] = nW4;
    ra.src[5] = (const float4*)Wv;    ra.dst[5] = (float4*)pWv; ra.n4[5] = nW4;
    ra.src[6] = (const float4*)Wo;    ra.dst[6] = (float4*)pWo; ra.n4[6] = nW4;
    round_all<<<dim3((nX4 + 255) / 256, 7), 256>>>(ra);

    dim3 ggrid(GN / 128, GM / 128);   // (8, 64)
    gemm_bias<<<ggrid, 256, GEMM_SMEM>>>(prQ, pWq, bq, pQ, 1);
    gemm_bias<<<ggrid, 256, GEMM_SMEM>>>(prK, pWk, bk, pK, 1);
    gemm_bias<<<ggrid, 256, GEMM_SMEM>>>(prV, pWv, bv, pV, 1);

    attn_kernel<<<dim3(SS / 128, HH, BB), 256, ATTN_SMEM>>>(pQ, pK, pV, pC);

    gemm_bias<<<ggrid, 256, GEMM_SMEM>>>(pC, pWo, bo, out, 0);
}

// round 4
// speedup vs baseline: 1.0076x; 1.0005x over previous
#include <cuda_runtime.h>
#include <cstdint>

// Problem constants
#define BB   4
#define SS   2048
#define DD   1024
#define HH   16
#define DKK  64

#define GM   (BB*SS)      // 8192
#define GK   DD
#define GN   DD

// ---------------------------------------------------------------------------
// Scratch (device globals)
// ---------------------------------------------------------------------------
__device__ float gQ[BB*SS*DD];
__device__ float gK[BB*SS*DD];
__device__ float gV[BB*SS*DD];
__device__ float gC[BB*SS*DD];
__device__ float rQi[BB*SS*DD];
__device__ float rKi[BB*SS*DD];
__device__ float rVi[BB*SS*DD];
__device__ float rWq[DD*DD];
__device__ float rWk[DD*DD];
__device__ float rWv[DD*DD];
__device__ float rWo[DD*DD];

// ---------------------------------------------------------------------------
// Helpers
// ---------------------------------------------------------------------------
__device__ __forceinline__ unsigned f2tf(float f) {
    unsigned r;
    asm("cvt.rna.tf32.f32 %0, %1;" : "=r"(r) : "f"(f));
    return r;
}
__device__ __forceinline__ float ex2(float x) {
    float r;
    asm("ex2.approx.ftz.f32 %0, %1;" : "=f"(r) : "f"(x));
    return r;
}
__device__ __forceinline__ void mma_tf32(float& d0, float& d1, float& d2, float& d3,
                                         unsigned a0, unsigned a1, unsigned a2, unsigned a3,
                                         unsigned b0, unsigned b1) {
    asm("mma.sync.aligned.m16n8k8.row.col.f32.tf32.tf32.f32 "
        "{%0,%1,%2,%3},{%4,%5,%6,%7},{%8,%9},{%0,%1,%2,%3};"
        : "+f"(d0), "+f"(d1), "+f"(d2), "+f"(d3)
        : "r"(a0), "r"(a1), "r"(a2), "r"(a3), "r"(b0), "r"(b1));
}

// ---------------------------------------------------------------------------
// One-launch rounding of all 7 tensors (RNA round to tf32-exact fp32).
// grid: (8192, 7). Segments 0-2: inputs (2M float4). 3-6: weights (256K).
// ---------------------------------------------------------------------------
struct RoundArgs {
    const float4* src[7];
    float4*       dst[7];
    int           n4[7];
};

__global__ __launch_bounds__(256)
void round_all(RoundArgs a) {
    int seg = blockIdx.y;
    int i = blockIdx.x * blockDim.x + threadIdx.x;
    if (i < a.n4[seg]) {
        float4 v = a.src[seg][i];
        v.x = __uint_as_float(f2tf(v.x));
        v.y = __uint_as_float(f2tf(v.y));
        v.z = __uint_as_float(f2tf(v.z));
        v.w = __uint_as_float(f2tf(v.w));
        a.dst[seg][i] = v;
    }
}

// ---------------------------------------------------------------------------
// GEMM: C[M,N] = X[M,K] @ W[K,N] + bias[N]; X,W pre-rounded tf32-exact fp32.
// Block tile 128x128x32, 256 thr, cp.async 2-stage double buffer.
// NOTE: no min-blocks clause — reg cap at 128 caused spills in round 2.
// ---------------------------------------------------------------------------
#define ASTR 36
#define BSTR 132
#define GEMM_SMEM ((2*128*ASTR + 2*32*BSTR) * 4)   // 70656 bytes

__global__ __launch_bounds__(256)
void gemm_bias(const float* __restrict__ X, const float* __restrict__ W,
               const float* __restrict__ bias, float* __restrict__ C, int round_out) {
    extern __shared__ unsigned gsm[];
    unsigned* As = gsm;                    // [2][128*ASTR]
    unsigned* Bs = gsm + 2 * 128 * ASTR;   // [2][32*BSTR]

    const int tid  = threadIdx.x;
    const int wid  = tid >> 5;
    const int lane = tid & 31;
    const int g    = lane >> 2;
    const int t    = lane & 3;
    const int wm   = wid & 1;
    const int wn   = wid >> 1;
    const int m0   = blockIdx.y * 128;
    const int n0   = blockIdx.x * 128;
    const int NKT  = GK / 32;

    float acc[4][4][4];
#pragma unroll
    for (int mf = 0; mf < 4; mf++)
#pragma unroll
        for (int nf = 0; nf < 4; nf++)
#pragma unroll
            for (int r = 0; r < 4; r++) acc[mf][nf][r] = 0.f;

    auto issue = [&](int s, int kt) {
#pragma unroll
        for (int i = 0; i < 4; i++) {
            int idx = tid + i * 256;
            int r = idx >> 3, c4 = idx & 7;
            const float* gp = X + (size_t)(m0 + r) * GK + kt * 32 + c4 * 4;
            unsigned sa = (unsigned)__cvta_generic_to_shared(&As[s * 128 * ASTR + r * ASTR + c4 * 4]);
            asm volatile("cp.async.cg.shared.global [%0], [%1], 16;" :: "r"(sa), "l"(gp));
        }
#pragma unroll
        for (int i = 0; i < 4; i++) {
            int idx = tid + i * 256;
            int r = idx >> 5, c4 = idx & 31;
            const float* gp = W + (size_t)(kt * 32 + r) * GN + n0 + c4 * 4;
            unsigned sa = (unsigned)__cvta_generic_to_shared(&Bs[s * 32 * BSTR + r * BSTR + c4 * 4]);
            asm volatile("cp.async.cg.shared.global [%0], [%1], 16;" :: "r"(sa), "l"(gp));
        }
        asm volatile("cp.async.commit_group;");
    };

    issue(0, 0);
    issue(1, 1);

    for (int kt = 0; kt < NKT; kt++) {
        asm volatile("cp.async.wait_group 1;");
        __syncthreads();
        const unsigned* Ag = As + (kt & 1) * 128 * ASTR;
        const unsigned* Bg = Bs + (kt & 1) * 32 * BSTR;

#pragma unroll
        for (int ks = 0; ks < 4; ks++) {
            unsigned a[4][4];
#pragma unroll
            for (int mf = 0; mf < 4; mf++) {
                int rb = wm * 64 + mf * 16;
                a[mf][0] = Ag[(rb + g)     * ASTR + ks * 8 + t];
                a[mf][1] = Ag[(rb + g + 8) * ASTR + ks * 8 + t];
                a[mf][2] = Ag[(rb + g)     * ASTR + ks * 8 + t + 4];
                a[mf][3] = Ag[(rb + g + 8) * ASTR + ks * 8 + t + 4];
            }
#pragma unroll
            for (int nf = 0; nf < 4; nf++) {
                unsigned b0 = Bg[(ks * 8 + t)     * BSTR + wn * 32 + nf * 8 + g];
                unsigned b1 = Bg[(ks * 8 + t + 4) * BSTR + wn * 32 + nf * 8 + g];
#pragma unroll
                for (int mf = 0; mf < 4; mf++)
                    mma_tf32(acc[mf][nf][0], acc[mf][nf][1], acc[mf][nf][2], acc[mf][nf][3],
                             a[mf][0], a[mf][1], a[mf][2], a[mf][3], b0, b1);
            }
        }
        __syncthreads();
        if (kt + 2 < NKT) issue(kt & 1, kt + 2);
        else asm volatile("cp.async.commit_group;");
    }

#pragma unroll
    for (int mf = 0; mf < 4; mf++) {
#pragma unroll
        for (int nf = 0; nf < 4; nf++) {
            int row = m0 + wm * 64 + mf * 16 + g;
            int col = n0 + wn * 32 + nf * 8 + 2 * t;
            float bv0 = bias[col], bv1 = bias[col + 1];
            float v00 = acc[mf][nf][0] + bv0;
            float v01 = acc[mf][nf][1] + bv1;
            float v10 = acc[mf][nf][2] + bv0;
            float v11 = acc[mf][nf][3] + bv1;
            if (round_out) {
                v00 = __uint_as_float(f2tf(v00));
                v01 = __uint_as_float(f2tf(v01));
                v10 = __uint_as_float(f2tf(v10));
                v11 = __uint_as_float(f2tf(v11));
            }
            C[(size_t)row * GN + col]           = v00;
            C[(size_t)row * GN + col + 1]       = v01;
            C[(size_t)(row + 8) * GN + col]     = v10;
            C[(size_t)(row + 8) * GN + col + 1] = v11;
        }
    }
}

// ---------------------------------------------------------------------------
// Flash attention v3: same dataflow as v2 but the S accumulator is converted
// to the PV A-fragment IN PLACE (no pa[] array) to avoid register spills.
// ---------------------------------------------------------------------------
#define KST 68
#define ATTN_SMEM ((128*KST + 128*KST) * 4)   // 69632 bytes

__global__ __launch_bounds__(256)
void attn_kernel(const float* __restrict__ gq, const float* __restrict__ gk,
                 const float* __restrict__ gv, float* __restrict__ gc) {
    extern __shared__ unsigned sm[];
    unsigned* Ks = sm;              // permuted [128][KST]
    unsigned* Vs = sm + 128 * KST;  // plain    [128][KST]

    const int b  = blockIdx.z;
    const int h  = blockIdx.y;
    const int q0 = blockIdx.x * 128;
    const int tid  = threadIdx.x;
    const int wid  = tid >> 5;
    const int lane = tid & 31;
    const int g    = lane >> 2;
    const int t    = lane & 3;
    const int qb   = lane & ~3;
    const float L2E = 1.44269504f;

    // Q fragments (pre-rounded; *0.125 exact in tf32)
    unsigned qf[8][4];
    {
        const float* Qb = gq + ((size_t)(b * SS + q0 + wid * 16)) * DD + h * DKK;
#pragma unroll
        for (int ks = 0; ks < 8; ks++) {
            qf[ks][0] = __float_as_uint(Qb[(size_t)g * DD + ks * 8 + t] * 0.125f);
            qf[ks][1] = __float_as_uint(Qb[(size_t)(g + 8) * DD + ks * 8 + t] * 0.125f);
            qf[ks][2] = __float_as_uint(Qb[(size_t)g * DD + ks * 8 + t + 4] * 0.125f);
            qf[ks][3] = __float_as_uint(Qb[(size_t)(g + 8) * DD + ks * 8 + t + 4] * 0.125f);
        }
    }

    float mr0 = -1e30f, mr1 = -1e30f, l0 = 0.f, l1 = 0.f;
    float oacc[8][4];
#pragma unroll
    for (int nf = 0; nf < 8; nf++)
#pragma unroll
        for (int r = 0; r < 4; r++) oacc[nf][r] = 0.f;

    const uint4* Kb = (const uint4*)(gk + (size_t)b * SS * DD + h * DKK);
    const uint4* Vb = (const uint4*)(gv + (size_t)b * SS * DD + h * DKK);
    const int RSTR4 = DD / 4;

    for (int kt = 0; kt < SS / 128; kt++) {
        __syncthreads();
#pragma unroll
        for (int i = 0; i < 8; i++) {
            int idx = tid + i * 256;
            int r = idx >> 4, c4 = idx & 15, c = c4 * 4;
            uint4 kv = Kb[(size_t)(kt * 128 + r) * RSTR4 + c4];
            int base = r * KST;
            Ks[base + ((c + 0) & 7) * 8 + ((c + 0) >> 3)] = kv.x;
            Ks[base + ((c + 1) & 7) * 8 + ((c + 1) >> 3)] = kv.y;
            Ks[base + ((c + 2) & 7) * 8 + ((c + 2) >> 3)] = kv.z;
            Ks[base + ((c + 3) & 7) * 8 + ((c + 3) >> 3)] = kv.w;
            uint4 vv = Vb[(size_t)(kt * 128 + r) * RSTR4 + c4];
            *(uint4*)&Vs[base + c] = vv;
        }
        __syncthreads();

        // S = Q K^T : 16 x 128 per warp
        float sacc[16][4];
#pragma unroll
        for (int nf = 0; nf < 16; nf++)
#pragma unroll
            for (int r = 0; r < 4; r++) sacc[nf][r] = 0.f;

#pragma unroll
        for (int nf = 0; nf < 16; nf++) {
            const uint4* kp = (const uint4*)&Ks[(nf * 8 + g) * KST + t * 8];
            uint4 k0 = kp[0], k1 = kp[1];
            const uint4* kq = (const uint4*)&Ks[(nf * 8 + g) * KST + (t + 4) * 8];
            uint4 k2 = kq[0], k3 = kq[1];
            mma_tf32(sacc[nf][0], sacc[nf][1], sacc[nf][2], sacc[nf][3],
                     qf[0][0], qf[0][1], qf[0][2], qf[0][3], k0.x, k2.x);
            mma_tf32(sacc[nf][0], sacc[nf][1], sacc[nf][2], sacc[nf][3],
                     qf[1][0], qf[1][1], qf[1][2], qf[1][3], k0.y, k2.y);
            mma_tf32(sacc[nf][0], sacc[nf][1], sacc[nf][2], sacc[nf][3],
                     qf[2][0], qf[2][1], qf[2][2], qf[2][3], k0.z, k2.z);
            mma_tf32(sacc[nf][0], sacc[nf][1], sacc[nf][2], sacc[nf][3],
                     qf[3][0], qf[3][1], qf[3][2], qf[3][3], k0.w, k2.w);
            mma_tf32(sacc[nf][0], sacc[nf][1], sacc[nf][2], sacc[nf][3],
                     qf[4][0], qf[4][1], qf[4][2], qf[4][3], k1.x, k3.x);
            mma_tf32(sacc[nf][0], sacc[nf][1], sacc[nf][2], sacc[nf][3],
                     qf[5][0], qf[5][1], qf[5][2], qf[5][3], k1.y, k3.y);
            mma_tf32(sacc[nf][0], sacc[nf][1], sacc[nf][2], sacc[nf][3],
                     qf[6][0], qf[6][1], qf[6][2], qf[6][3], k1.z, k3.z);
            mma_tf32(sacc[nf][0], sacc[nf][1], sacc[nf][2], sacc[nf][3],
                     qf[7][0], qf[7][1], qf[7][2], qf[7][3], k1.w, k3.w);
        }

        // online softmax
        float rmax0 = -1e30f, rmax1 = -1e30f;
#pragma unroll
        for (int nf = 0; nf < 16; nf++) {
            rmax0 = fmaxf(rmax0, fmaxf(sacc[nf][0], sacc[nf][1]));
            rmax1 = fmaxf(rmax1, fmaxf(sacc[nf][2], sacc[nf][3]));
        }
        rmax0 = fmaxf(rmax0, __shfl_xor_sync(0xffffffffu, rmax0, 1));
        rmax0 = fmaxf(rmax0, __shfl_xor_sync(0xffffffffu, rmax0, 2));
        rmax1 = fmaxf(rmax1, __shfl_xor_sync(0xffffffffu, rmax1, 1));
        rmax1 = fmaxf(rmax1, __shfl_xor_sync(0xffffffffu, rmax1, 2));
        float mn0 = fmaxf(mr0, rmax0), mn1 = fmaxf(mr1, rmax1);
        float alpha0 = ex2((mr0 - mn0) * L2E);
        float alpha1 = ex2((mr1 - mn1) * L2E);
        mr0 = mn0; mr1 = mn1;

        // exp + quad-shuffle; convert sacc fragment -> A-fragment IN PLACE
        float rs0 = 0.f, rs1 = 0.f;
        const int s0 = qb | (t >> 1);
        const int s1 = s0 + 2;
        const bool odd = (t & 1);
#pragma unroll
        for (int nf = 0; nf < 16; nf++) {
            float p0 = ex2((sacc[nf][0] - mn0) * L2E);
            float p1 = ex2((sacc[nf][1] - mn0) * L2E);
            float p2 = ex2((sacc[nf][2] - mn1) * L2E);
            float p3 = ex2((sacc[nf][3] - mn1) * L2E);
            rs0 += p0 + p1;
            rs1 += p2 + p3;
            float y00 = __shfl_sync(0xffffffffu, p0, s0);
            float y01 = __shfl_sync(0xffffffffu, p1, s0);
            float y10 = __shfl_sync(0xffffffffu, p2, s0);
            float y11 = __shfl_sync(0xffffffffu, p3, s0);
            float z00 = __shfl_sync(0xffffffffu, p0, s1);
            float z01 = __shfl_sync(0xffffffffu, p1, s1);
            float z10 = __shfl_sync(0xffffffffu, p2, s1);
            float z11 = __shfl_sync(0xffffffffu, p3, s1);
            sacc[nf][0] = __uint_as_float(f2tf(odd ? y01 : y00));
            sacc[nf][1] = __uint_as_float(f2tf(odd ? y11 : y10));
            sacc[nf][2] = __uint_as_float(f2tf(odd ? z01 : z00));
            sacc[nf][3] = __uint_as_float(f2tf(odd ? z11 : z10));
        }
        rs0 += __shfl_xor_sync(0xffffffffu, rs0, 1);
        rs0 += __shfl_xor_sync(0xffffffffu, rs0, 2);
        rs1 += __shfl_xor_sync(0xffffffffu, rs1, 1);
        rs1 += __shfl_xor_sync(0xffffffffu, rs1, 2);
        l0 = l0 * alpha0 + rs0;
        l1 = l1 * alpha1 + rs1;
#pragma unroll
        for (int nf = 0; nf < 8; nf++) {
            oacc[nf][0] *= alpha0; oacc[nf][1] *= alpha0;
            oacc[nf][2] *= alpha1; oacc[nf][3] *= alpha1;
        }

        // O += P V  (A fragments read from the converted sacc)
#pragma unroll
        for (int nf = 0; nf < 8; nf++) {
#pragma unroll
            for (int ks = 0; ks < 16; ks++) {
                unsigned a0 = __float_as_uint(sacc[ks][0]);
                unsigned a1 = __float_as_uint(sacc[ks][1]);
                unsigned a2 = __float_as_uint(sacc[ks][2]);
                unsigned a3 = __float_as_uint(sacc[ks][3]);
                unsigned b0 = Vs[(ks * 8 + t)     * KST + nf * 8 + g];
                unsigned b1 = Vs[(ks * 8 + t + 4) * KST + nf * 8 + g];
                mma_tf32(oacc[nf][0], oacc[nf][1], oacc[nf][2], oacc[nf][3],
                         a0, a1, a2, a3, b0, b1);
            }
        }
    }

    // epilogue: normalize + round (ctx feeds the tf32 O-projection)
    float inv0 = 1.f / l0, inv1 = 1.f / l1;
    float* Cb = gc + ((size_t)(b * SS + q0 + wid * 16)) * DD + h * DKK;
#pragma unroll
    for (int nf = 0; nf < 8; nf++) {
        int c = nf * 8 + 2 * t;
        Cb[(size_t)g * DD + c]           = __uint_as_float(f2tf(oacc[nf][0] * inv0));
        Cb[(size_t)g * DD + c + 1]       = __uint_as_float(f2tf(oacc[nf][1] * inv0));
        Cb[(size_t)(g + 8) * DD + c]     = __uint_as_float(f2tf(oacc[nf][2] * inv1));
        Cb[(size_t)(g + 8) * DD + c + 1] = __uint_as_float(f2tf(oacc[nf][3] * inv1));
    }
}

// ---------------------------------------------------------------------------
// Launch
// ---------------------------------------------------------------------------
extern "C" void kernel_launch(void* const* d_in, const int* in_sizes, int n_in,
                              void* d_out, int out_size) {
    const float* query = (const float*)d_in[0];
    const float* key_  = (const float*)d_in[1];
    const float* value = (const float*)d_in[2];
    const float* Wq = (const float*)d_in[3];
    const float* bq = (const float*)d_in[4];
    const float* Wk = (const float*)d_in[5];
    const float* bk = (const float*)d_in[6];
    const float* Wv = (const float*)d_in[7];
    const float* bv = (const float*)d_in[8];
    const float* Wo = (const float*)d_in[9];
    const float* bo = (const float*)d_in[10];
    float* out = (float*)d_out;

    float *pQ, *pK, *pV, *pC, *prQ, *prK, *prV, *pWq, *pWk, *pWv, *pWo;
    cudaGetSymbolAddress((void**)&pQ, gQ);
    cudaGetSymbolAddress((void**)&pK, gK);
    cudaGetSymbolAddress((void**)&pV, gV);
    cudaGetSymbolAddress((void**)&pC, gC);
    cudaGetSymbolAddress((void**)&prQ, rQi);
    cudaGetSymbolAddress((void**)&prK, rKi);
    cudaGetSymbolAddress((void**)&prV, rVi);
    cudaGetSymbolAddress((void**)&pWq, rWq);
    cudaGetSymbolAddress((void**)&pWk, rWk);
    cudaGetSymbolAddress((void**)&pWv, rWv);
    cudaGetSymbolAddress((void**)&pWo, rWo);

    cudaFuncSetAttribute(gemm_bias, cudaFuncAttributeMaxDynamicSharedMemorySize, GEMM_SMEM);
    cudaFuncSetAttribute(attn_kernel, cudaFuncAttributeMaxDynamicSharedMemorySize, ATTN_SMEM);

    const int nX4 = GM * DD / 4, nW4 = DD * DD / 4;
    RoundArgs ra;
    ra.src[0] = (const float4*)query; ra.dst[0] = (float4*)prQ; ra.n4[0] = nX4;
    ra.src[1] = (const float4*)key_;  ra.dst[1] = (float4*)prK; ra.n4[1] = nX4;
    ra.src[2] = (const float4*)value; ra.dst[2] = (float4*)prV; ra.n4[2] = nX4;
    ra.src[3] = (const float4*)Wq;    ra.dst[3] = (float4*)pWq; ra.n4[3] = nW4;
    ra.src[4] = (const float4*)Wk;    ra.dst[4] = (float4*)pWk; ra.n4[4] = nW4;
    ra.src[5] = (const float4*)Wv;    ra.dst[5] = (float4*)pWv; ra.n4[5] = nW4;
    ra.src[6] = (const float4*)Wo;    ra.dst[6] = (float4*)pWo; ra.n4[6] = nW4;
    round_all<<<dim3((nX4 + 255) / 256, 7), 256>>>(ra);

    dim3 ggrid(GN / 128, GM / 128);   // (8, 64)
    gemm_bias<<<ggrid, 256, GEMM_SMEM>>>(prQ, pWq, bq, pQ, 1);
    gemm_bias<<<ggrid, 256, GEMM_SMEM>>>(prK, pWk, bk, pK, 1);
    gemm_bias<<<ggrid, 256, GEMM_SMEM>>>(prV, pWv, bv, pV, 1);

    attn_kernel<<<dim3(SS / 128, HH, BB), 256, ATTN_SMEM>>>(pQ, pK, pV, pC);

    gemm_bias<<<ggrid, 256, GEMM_SMEM>>>(pC, pWo, bo, out, 0);
}

// round 6
// speedup vs baseline: 1.1166x; 1.1081x over previous
#include <cuda_runtime.h>
#include <cstdint>

#define BB   4
#define SS   2048
#define DD   1024
#define HH   16
#define DKK  64
#define GM   (BB*SS)
#define GK   DD
#define GN   DD

// ---------------------------------------------------------------------------
// Scratch (device globals; allocation-free per harness rules)
// ---------------------------------------------------------------------------
__device__ float gQ[BB*SS*DD];
__device__ float gK[BB*SS*DD];
__device__ float gV[BB*SS*DD];
__device__ float gC[BB*SS*DD];

// ---------------------------------------------------------------------------
// Helpers
// ---------------------------------------------------------------------------
__device__ __forceinline__ unsigned f2tf(float f) {
    unsigned r;
    asm("cvt.rna.tf32.f32 %0, %1;" : "=r"(r) : "f"(f));
    return r;
}
__device__ __forceinline__ float ex2(float x) {
    float r;
    asm("ex2.approx.ftz.f32 %0, %1;" : "=f"(r) : "f"(x));
    return r;
}
__device__ __forceinline__ void mma_tf32(float& d0, float& d1, float& d2, float& d3,
                                         unsigned a0, unsigned a1, unsigned a2, unsigned a3,
                                         unsigned b0, unsigned b1) {
    asm("mma.sync.aligned.m16n8k8.row.col.f32.tf32.tf32.f32 "
        "{%0,%1,%2,%3},{%4,%5,%6,%7},{%8,%9},{%0,%1,%2,%3};"
        : "+f"(d0), "+f"(d1), "+f"(d2), "+f"(d3)
        : "r"(a0), "r"(a1), "r"(a2), "r"(a3), "r"(b0), "r"(b1));
}

// ---------------------------------------------------------------------------
// GEMM: C[M,N] = round(X)[M,K] @ round(W)[K,N] + bias[N]
// Block tile 128x128x32, 256 thr (8 warps, warp 64x32). Round-1 structure
// (LDG -> f2tf -> STS staging): proven 139us; cp.async variant identical.
// round_out=1 rounds the fp32 result to tf32-exact bits for downstream mma.
// ---------------------------------------------------------------------------
#define ASTR 36
#define BSTR 132

__global__ __launch_bounds__(256)
void gemm_bias(const float* __restrict__ X, const float* __restrict__ W,
               const float* __restrict__ bias, float* __restrict__ C, int round_out) {
    __shared__ unsigned As[128 * ASTR];
    __shared__ unsigned Bs[32 * BSTR];

    const int tid  = threadIdx.x;
    const int wid  = tid >> 5;
    const int lane = tid & 31;
    const int g    = lane >> 2;
    const int t    = lane & 3;
    const int wm   = wid & 1;
    const int wn   = wid >> 1;
    const int m0   = blockIdx.y * 128;
    const int n0   = blockIdx.x * 128;

    float acc[4][4][4];
#pragma unroll
    for (int mf = 0; mf < 4; mf++)
#pragma unroll
        for (int nf = 0; nf < 4; nf++)
#pragma unroll
            for (int r = 0; r < 4; r++) acc[mf][nf][r] = 0.f;

    for (int kt = 0; kt < GK / 32; kt++) {
        __syncthreads();
#pragma unroll
        for (int i = 0; i < 4; i++) {
            int idx = tid + i * 256;
            int r = idx >> 3, c4 = idx & 7;
            float4 v = *(const float4*)(X + (size_t)(m0 + r) * GK + kt * 32 + c4 * 4);
            unsigned* dst = &As[r * ASTR + c4 * 4];
            dst[0] = f2tf(v.x); dst[1] = f2tf(v.y); dst[2] = f2tf(v.z); dst[3] = f2tf(v.w);
        }
#pragma unroll
        for (int i = 0; i < 4; i++) {
            int idx = tid + i * 256;
            int r = idx >> 5, c4 = idx & 31;
            float4 v = *(const float4*)(W + (size_t)(kt * 32 + r) * GN + n0 + c4 * 4);
            unsigned* dst = &Bs[r * BSTR + c4 * 4];
            dst[0] = f2tf(v.x); dst[1] = f2tf(v.y); dst[2] = f2tf(v.z); dst[3] = f2tf(v.w);
        }
        __syncthreads();

#pragma unroll
        for (int ks = 0; ks < 4; ks++) {
            unsigned a[4][4];
#pragma unroll
            for (int mf = 0; mf < 4; mf++) {
                int rb = wm * 64 + mf * 16;
                a[mf][0] = As[(rb + g)     * ASTR + ks * 8 + t];
                a[mf][1] = As[(rb + g + 8) * ASTR + ks * 8 + t];
                a[mf][2] = As[(rb + g)     * ASTR + ks * 8 + t + 4];
                a[mf][3] = As[(rb + g + 8) * ASTR + ks * 8 + t + 4];
            }
#pragma unroll
            for (int nf = 0; nf < 4; nf++) {
                unsigned b0 = Bs[(ks * 8 + t)     * BSTR + wn * 32 + nf * 8 + g];
                unsigned b1 = Bs[(ks * 8 + t + 4) * BSTR + wn * 32 + nf * 8 + g];
#pragma unroll
                for (int mf = 0; mf < 4; mf++)
                    mma_tf32(acc[mf][nf][0], acc[mf][nf][1], acc[mf][nf][2], acc[mf][nf][3],
                             a[mf][0], a[mf][1], a[mf][2], a[mf][3], b0, b1);
            }
        }
    }

#pragma unroll
    for (int mf = 0; mf < 4; mf++) {
#pragma unroll
        for (int nf = 0; nf < 4; nf++) {
            int row = m0 + wm * 64 + mf * 16 + g;
            int col = n0 + wn * 32 + nf * 8 + 2 * t;
            float bv0 = bias[col], bv1 = bias[col + 1];
            float v00 = acc[mf][nf][0] + bv0;
            float v01 = acc[mf][nf][1] + bv1;
            float v10 = acc[mf][nf][2] + bv0;
            float v11 = acc[mf][nf][3] + bv1;
            if (round_out) {
                v00 = __uint_as_float(f2tf(v00));
                v01 = __uint_as_float(f2tf(v01));
                v10 = __uint_as_float(f2tf(v10));
                v11 = __uint_as_float(f2tf(v11));
            }
            C[(size_t)row * GN + col]           = v00;
            C[(size_t)row * GN + col + 1]       = v01;
            C[(size_t)(row + 8) * GN + col]     = v10;
            C[(size_t)(row + 8) * GN + col + 1] = v11;
        }
    }
}

// ---------------------------------------------------------------------------
// Flash attention v5: v3 dataflow, V stride bumped 68 -> 72 so PV B-fragment
// LDS.32s (bank = 8t+g, distinct over the warp) are conflict-free. K stays 68
// (its LDS.128 phase pattern g+2ks needs stride==4 mod 8).
// ---------------------------------------------------------------------------
#define KST 68
#define VST 72
#define ATTN_SMEM ((128*KST + 128*VST) * 4)   // 71680 bytes

__global__ __launch_bounds__(256)
void attn_kernel(const float* __restrict__ gq, const float* __restrict__ gk,
                 const float* __restrict__ gv, float* __restrict__ gc) {
    extern __shared__ unsigned sm[];
    unsigned* Ks = sm;              // k-permuted [128][KST]
    unsigned* Vs = sm + 128 * KST;  // plain      [128][VST]

    const int b  = blockIdx.z;
    const int h  = blockIdx.y;
    const int q0 = blockIdx.x * 128;
    const int tid  = threadIdx.x;
    const int wid  = tid >> 5;
    const int lane = tid & 31;
    const int g    = lane >> 2;
    const int t    = lane & 3;
    const int qb   = lane & ~3;
    const float L2E = 1.44269504f;

    // Q fragments (inputs are tf32-exact; *0.125 exact)
    unsigned qf[8][4];
    {
        const float* Qb = gq + ((size_t)(b * SS + q0 + wid * 16)) * DD + h * DKK;
#pragma unroll
        for (int ks = 0; ks < 8; ks++) {
            qf[ks][0] = __float_as_uint(Qb[(size_t)g * DD + ks * 8 + t] * 0.125f);
            qf[ks][1] = __float_as_uint(Qb[(size_t)(g + 8) * DD + ks * 8 + t] * 0.125f);
            qf[ks][2] = __float_as_uint(Qb[(size_t)g * DD + ks * 8 + t + 4] * 0.125f);
            qf[ks][3] = __float_as_uint(Qb[(size_t)(g + 8) * DD + ks * 8 + t + 4] * 0.125f);
        }
    }

    float mr0 = -1e30f, mr1 = -1e30f, l0 = 0.f, l1 = 0.f;
    float oacc[8][4];
#pragma unroll
    for (int nf = 0; nf < 8; nf++)
#pragma unroll
        for (int r = 0; r < 4; r++) oacc[nf][r] = 0.f;

    const uint4* Kb = (const uint4*)(gk + (size_t)b * SS * DD + h * DKK);
    const uint4* Vb = (const uint4*)(gv + (size_t)b * SS * DD + h * DKK);
    const int RSTR4 = DD / 4;

    for (int kt = 0; kt < SS / 128; kt++) {
        __syncthreads();
#pragma unroll
        for (int i = 0; i < 8; i++) {
            int idx = tid + i * 256;
            int r = idx >> 4, c4 = idx & 15, c = c4 * 4;
            uint4 kv = Kb[(size_t)(kt * 128 + r) * RSTR4 + c4];
            int kbase = r * KST;
            Ks[kbase + ((c + 0) & 7) * 8 + ((c + 0) >> 3)] = kv.x;
            Ks[kbase + ((c + 1) & 7) * 8 + ((c + 1) >> 3)] = kv.y;
            Ks[kbase + ((c + 2) & 7) * 8 + ((c + 2) >> 3)] = kv.z;
            Ks[kbase + ((c + 3) & 7) * 8 + ((c + 3) >> 3)] = kv.w;
            uint4 vv = Vb[(size_t)(kt * 128 + r) * RSTR4 + c4];
            *(uint4*)&Vs[r * VST + c] = vv;
        }
        __syncthreads();

        // S = Q K^T : 16 x 128 per warp
        float sacc[16][4];
#pragma unroll
        for (int nf = 0; nf < 16; nf++)
#pragma unroll
            for (int r = 0; r < 4; r++) sacc[nf][r] = 0.f;

#pragma unroll
        for (int nf = 0; nf < 16; nf++) {
            const uint4* kp = (const uint4*)&Ks[(nf * 8 + g) * KST + t * 8];
            uint4 k0 = kp[0], k1 = kp[1];
            const uint4* kq = (const uint4*)&Ks[(nf * 8 + g) * KST + (t + 4) * 8];
            uint4 k2 = kq[0], k3 = kq[1];
            mma_tf32(sacc[nf][0], sacc[nf][1], sacc[nf][2], sacc[nf][3],
                     qf[0][0], qf[0][1], qf[0][2], qf[0][3], k0.x, k2.x);
            mma_tf32(sacc[nf][0], sacc[nf][1], sacc[nf][2], sacc[nf][3],
                     qf[1][0], qf[1][1], qf[1][2], qf[1][3], k0.y, k2.y);
            mma_tf32(sacc[nf][0], sacc[nf][1], sacc[nf][2], sacc[nf][3],
                     qf[2][0], qf[2][1], qf[2][2], qf[2][3], k0.z, k2.z);
            mma_tf32(sacc[nf][0], sacc[nf][1], sacc[nf][2], sacc[nf][3],
                     qf[3][0], qf[3][1], qf[3][2], qf[3][3], k0.w, k2.w);
            mma_tf32(sacc[nf][0], sacc[nf][1], sacc[nf][2], sacc[nf][3],
                     qf[4][0], qf[4][1], qf[4][2], qf[4][3], k1.x, k3.x);
            mma_tf32(sacc[nf][0], sacc[nf][1], sacc[nf][2], sacc[nf][3],
                     qf[5][0], qf[5][1], qf[5][2], qf[5][3], k1.y, k3.y);
            mma_tf32(sacc[nf][0], sacc[nf][1], sacc[nf][2], sacc[nf][3],
                     qf[6][0], qf[6][1], qf[6][2], qf[6][3], k1.z, k3.z);
            mma_tf32(sacc[nf][0], sacc[nf][1], sacc[nf][2], sacc[nf][3],
                     qf[7][0], qf[7][1], qf[7][2], qf[7][3], k1.w, k3.w);
        }

        // online softmax
        float rmax0 = -1e30f, rmax1 = -1e30f;
#pragma unroll
        for (int nf = 0; nf < 16; nf++) {
            rmax0 = fmaxf(rmax0, fmaxf(sacc[nf][0], sacc[nf][1]));
            rmax1 = fmaxf(rmax1, fmaxf(sacc[nf][2], sacc[nf][3]));
        }
        rmax0 = fmaxf(rmax0, __shfl_xor_sync(0xffffffffu, rmax0, 1));
        rmax0 = fmaxf(rmax0, __shfl_xor_sync(0xffffffffu, rmax0, 2));
        rmax1 = fmaxf(rmax1, __shfl_xor_sync(0xffffffffu, rmax1, 1));
        rmax1 = fmaxf(rmax1, __shfl_xor_sync(0xffffffffu, rmax1, 2));
        float mn0 = fmaxf(mr0, rmax0), mn1 = fmaxf(mr1, rmax1);
        float alpha0 = ex2((mr0 - mn0) * L2E);
        float alpha1 = ex2((mr1 - mn1) * L2E);
        mr0 = mn0; mr1 = mn1;

        // exp + quad-shuffle; convert sacc fragment -> PV A-fragment in place
        float rs0 = 0.f, rs1 = 0.f;
        const int s0 = qb | (t >> 1);
        const int s1 = s0 + 2;
        const bool odd = (t & 1);
#pragma unroll
        for (int nf = 0; nf < 16; nf++) {
            float p0 = ex2((sacc[nf][0] - mn0) * L2E);
            float p1 = ex2((sacc[nf][1] - mn0) * L2E);
            float p2 = ex2((sacc[nf][2] - mn1) * L2E);
            float p3 = ex2((sacc[nf][3] - mn1) * L2E);
            rs0 += p0 + p1;
            rs1 += p2 + p3;
            float y00 = __shfl_sync(0xffffffffu, p0, s0);
            float y01 = __shfl_sync(0xffffffffu, p1, s0);
            float y10 = __shfl_sync(0xffffffffu, p2, s0);
            float y11 = __shfl_sync(0xffffffffu, p3, s0);
            float z00 = __shfl_sync(0xffffffffu, p0, s1);
            float z01 = __shfl_sync(0xffffffffu, p1, s1);
            float z10 = __shfl_sync(0xffffffffu, p2, s1);
            float z11 = __shfl_sync(0xffffffffu, p3, s1);
            sacc[nf][0] = __uint_as_float(f2tf(odd ? y01 : y00));
            sacc[nf][1] = __uint_as_float(f2tf(odd ? y11 : y10));
            sacc[nf][2] = __uint_as_float(f2tf(odd ? z01 : z00));
            sacc[nf][3] = __uint_as_float(f2tf(odd ? z11 : z10));
        }
        rs0 += __shfl_xor_sync(0xffffffffu, rs0, 1);
        rs0 += __shfl_xor_sync(0xffffffffu, rs0, 2);
        rs1 += __shfl_xor_sync(0xffffffffu, rs1, 1);
        rs1 += __shfl_xor_sync(0xffffffffu, rs1, 2);
        l0 = l0 * alpha0 + rs0;
        l1 = l1 * alpha1 + rs1;
#pragma unroll
        for (int nf = 0; nf < 8; nf++) {
            oacc[nf][0] *= alpha0; oacc[nf][1] *= alpha0;
            oacc[nf][2] *= alpha1; oacc[nf][3] *= alpha1;
        }

        // O += P V  (conflict-free B-fragment loads, stride 72)
#pragma unroll
        for (int nf = 0; nf < 8; nf++) {
#pragma unroll
            for (int ks = 0; ks < 16; ks++) {
                unsigned a0 = __float_as_uint(sacc[ks][0]);
                unsigned a1 = __float_as_uint(sacc[ks][1]);
                unsigned a2 = __float_as_uint(sacc[ks][2]);
                unsigned a3 = __float_as_uint(sacc[ks][3]);
                unsigned b0 = Vs[(ks * 8 + t)     * VST + nf * 8 + g];
                unsigned b1 = Vs[(ks * 8 + t + 4) * VST + nf * 8 + g];
                mma_tf32(oacc[nf][0], oacc[nf][1], oacc[nf][2], oacc[nf][3],
                         a0, a1, a2, a3, b0, b1);
            }
        }
    }

    // epilogue: normalize + round (ctx feeds the tf32 O-projection)
    float inv0 = 1.f / l0, inv1 = 1.f / l1;
    float* Cb = gc + ((size_t)(b * SS + q0 + wid * 16)) * DD + h * DKK;
#pragma unroll
    for (int nf = 0; nf < 8; nf++) {
        int c = nf * 8 + 2 * t;
        Cb[(size_t)g * DD + c]           = __uint_as_float(f2tf(oacc[nf][0] * inv0));
        Cb[(size_t)g * DD + c + 1]       = __uint_as_float(f2tf(oacc[nf][1] * inv0));
        Cb[(size_t)(g + 8) * DD + c]     = __uint_as_float(f2tf(oacc[nf][2] * inv1));
        Cb[(size_t)(g + 8) * DD + c + 1] = __uint_as_float(f2tf(oacc[nf][3] * inv1));
    }
}

// ---------------------------------------------------------------------------
// Launch: 5 kernels, no prepass.
// ---------------------------------------------------------------------------
extern "C" void kernel_launch(void* const* d_in, const int* in_sizes, int n_in,
                              void* d_out, int out_size) {
    const float* query = (const float*)d_in[0];
    const float* key_  = (const float*)d_in[1];
    const float* value = (const float*)d_in[2];
    const float* Wq = (const float*)d_in[3];
    const float* bq = (const float*)d_in[4];
    const float* Wk = (const float*)d_in[5];
    const float* bk = (const float*)d_in[6];
    const float* Wv = (const float*)d_in[7];
    const float* bv = (const float*)d_in[8];
    const float* Wo = (const float*)d_in[9];
    const float* bo = (const float*)d_in[10];
    float* out = (float*)d_out;

    float *pQ, *pK, *pV, *pC;
    cudaGetSymbolAddress((void**)&pQ, gQ);
    cudaGetSymbolAddress((void**)&pK, gK);
    cudaGetSymbolAddress((void**)&pV, gV);
    cudaGetSymbolAddress((void**)&pC, gC);

    cudaFuncSetAttribute(attn_kernel, cudaFuncAttributeMaxDynamicSharedMemorySize, ATTN_SMEM);

    dim3 ggrid(GN / 128, GM / 128);   // (8, 64)
    gemm_bias<<<ggrid, 256>>>(query, Wq, bq, pQ, 1);
    gemm_bias<<<ggrid, 256>>>(key_,  Wk, bk, pK, 1);
    gemm_bias<<<ggrid, 256>>>(value, Wv, bv, pV, 1);

    attn_kernel<<<dim3(SS / 128, HH, BB), 256, ATTN_SMEM>>>(pQ, pK, pV, pC);

    gemm_bias<<<ggrid, 256>>>(pC, Wo, bo, out, 0);
}